// round 2
// baseline (speedup 1.0000x reference)
#include <cuda_runtime.h>
#include <math.h>

// Problem constants
#define B_    128
#define T_    512
#define C_    512
#define H_    512
#define PT_   16
#define SKIP_ 32
#define NSEQ  4096        // B_*SKIP_
#define G3    1536        // 3*H_

// Tiling
#define BM 128
#define BN 32
#define BK 16
#define TM 8
#define TN 2
#define NTHREADS 256      // (BM/TM)*(BN/TN)

// Ping-pong hidden-state scratch (device globals: no allocations allowed)
__device__ float g_hA[NSEQ * H_];
__device__ float g_hB[NSEQ * H_];

// One GRU step, fused: acc = x_t @ W  (phase 0)  +  h @ U  (phase 1), then gates.
// Gate layout in W/U/b columns: [z | r | h] each H_ wide.
// z,r accumulate across both phases; xh (from x@W) and rh (from h@U) stay separate
// because hh = relu(xh + r*rh).
__global__ __launch_bounds__(NTHREADS)
void gru_step_kernel(const float* __restrict__ x,
                     const float* __restrict__ W,
                     const float* __restrict__ U,
                     const float* __restrict__ b,     // [2][1536]
                     const float* __restrict__ hin,
                     float* __restrict__ hout,
                     int t, int first)
{
    __shared__ float As[BK][BM + 1];     // +1 pad: transposed stores, 2-way max conflict
    __shared__ float Bs[3][BK][BN];

    const int tid   = threadIdx.x;
    const int tileN = blockIdx.x * BN;   // output column j base (0..511)
    const int tileM = blockIdx.y * BM;   // sequence row base  (0..4095)

    const int ty = tid >> 4;             // 0..15 row group
    const int tx = tid & 15;             // 0..15 col group

    const int aRow = tid >> 2;           // 0..63
    const int aCol = (tid & 3) * 4;      // 0,4,8,12

    float accz[TM][TN], accr[TM][TN], accxh[TM][TN], accrh[TM][TN];
    #pragma unroll
    for (int i = 0; i < TM; ++i)
        #pragma unroll
        for (int j = 0; j < TN; ++j) {
            accz[i][j] = 0.f; accr[i][j] = 0.f;
            accxh[i][j] = 0.f; accrh[i][j] = 0.f;
        }

    // ---------------- Phase 0: x_t @ W -> accz, accr, accxh ----------------
    for (int kt = 0; kt < C_ / BK; ++kt) {
        const int k0 = kt * BK;
        // A tile: gathered x rows. row m -> x[b, t*32 + k, :], b=m>>5, k=m&31
        #pragma unroll
        for (int p = 0; p < 2; ++p) {
            const int r  = aRow + p * 64;
            const int m  = tileM + r;
            const int bb = m >> 5;
            const int kk = m & 31;
            const float4 v = *(const float4*)(x + ((size_t)bb * T_ + (size_t)(t * SKIP_ + kk)) * C_ + k0 + aCol);
            As[aCol + 0][r] = v.x;
            As[aCol + 1][r] = v.y;
            As[aCol + 2][r] = v.z;
            As[aCol + 3][r] = v.w;
        }
        // B tile: W rows k0..k0+15, 3 gate column blocks of BN each
        #pragma unroll
        for (int i = 0; i < 6; ++i) {
            const int idx = i * NTHREADS + tid;      // 0..1535
            const int g   = idx >> 9;
            const int rem = idx & 511;
            const int kr  = rem >> 5;
            const int c   = rem & 31;
            Bs[g][kr][c] = W[(size_t)(k0 + kr) * G3 + g * H_ + tileN + c];
        }
        __syncthreads();
        #pragma unroll
        for (int kk = 0; kk < BK; ++kk) {
            float a_frag[TM];
            #pragma unroll
            for (int i = 0; i < TM; ++i) a_frag[i] = As[kk][ty * TM + i];
            float bz[TN], br[TN], bh[TN];
            #pragma unroll
            for (int j = 0; j < TN; ++j) {
                bz[j] = Bs[0][kk][tx * TN + j];
                br[j] = Bs[1][kk][tx * TN + j];
                bh[j] = Bs[2][kk][tx * TN + j];
            }
            #pragma unroll
            for (int i = 0; i < TM; ++i)
                #pragma unroll
                for (int j = 0; j < TN; ++j) {
                    accz [i][j] += a_frag[i] * bz[j];
                    accr [i][j] += a_frag[i] * br[j];
                    accxh[i][j] += a_frag[i] * bh[j];
                }
        }
        __syncthreads();
    }

    // ---------------- Phase 1: h @ U -> accz, accr, accrh ----------------
    if (!first) {
        for (int kt = 0; kt < H_ / BK; ++kt) {
            const int k0 = kt * BK;
            #pragma unroll
            for (int p = 0; p < 2; ++p) {
                const int r = aRow + p * 64;
                const int m = tileM + r;
                const float4 v = *(const float4*)(hin + (size_t)m * H_ + k0 + aCol);
                As[aCol + 0][r] = v.x;
                As[aCol + 1][r] = v.y;
                As[aCol + 2][r] = v.z;
                As[aCol + 3][r] = v.w;
            }
            #pragma unroll
            for (int i = 0; i < 6; ++i) {
                const int idx = i * NTHREADS + tid;
                const int g   = idx >> 9;
                const int rem = idx & 511;
                const int kr  = rem >> 5;
                const int c   = rem & 31;
                Bs[g][kr][c] = U[(size_t)(k0 + kr) * G3 + g * H_ + tileN + c];
            }
            __syncthreads();
            #pragma unroll
            for (int kk = 0; kk < BK; ++kk) {
                float a_frag[TM];
                #pragma unroll
                for (int i = 0; i < TM; ++i) a_frag[i] = As[kk][ty * TM + i];
                float bz[TN], br[TN], bh[TN];
                #pragma unroll
                for (int j = 0; j < TN; ++j) {
                    bz[j] = Bs[0][kk][tx * TN + j];
                    br[j] = Bs[1][kk][tx * TN + j];
                    bh[j] = Bs[2][kk][tx * TN + j];
                }
                #pragma unroll
                for (int i = 0; i < TM; ++i)
                    #pragma unroll
                    for (int j = 0; j < TN; ++j) {
                        accz [i][j] += a_frag[i] * bz[j];
                        accr [i][j] += a_frag[i] * br[j];
                        accrh[i][j] += a_frag[i] * bh[j];
                    }
            }
            __syncthreads();
        }
    }

    // ---------------- Epilogue: gates + state update ----------------
    #pragma unroll
    for (int i = 0; i < TM; ++i) {
        const int m = tileM + ty * TM + i;
        #pragma unroll
        for (int j = 0; j < TN; ++j) {
            const int col = tileN + tx * TN + j;
            const float preZ = accz[i][j] + b[col]            + b[G3 + col];
            const float preR = accr[i][j] + b[H_ + col]       + b[G3 + H_ + col];
            const float xh   = accxh[i][j] + b[2 * H_ + col];
            const float rh   = accrh[i][j] + b[G3 + 2 * H_ + col];
            const float z  = 1.f / (1.f + __expf(-preZ));
            const float r  = 1.f / (1.f + __expf(-preR));
            const float hh = fmaxf(xh + r * rh, 0.f);
            const float hp = first ? 0.f : hin[(size_t)m * H_ + col];
            hout[(size_t)m * H_ + col] = z * hp + (1.f - z) * hh;
        }
    }
}

extern "C" void kernel_launch(void* const* d_in, const int* in_sizes, int n_in,
                              void* d_out, int out_size) {
    const float* x = (const float*)d_in[0];   // (128, 512, 512)
    const float* W = (const float*)d_in[1];   // (512, 1536)
    const float* U = (const float*)d_in[2];   // (512, 1536)
    const float* b = (const float*)d_in[3];   // (2, 1536)
    float* out = (float*)d_out;               // (128, 16384) == flat [n][h]

    float *hA = nullptr, *hB = nullptr;
    cudaGetSymbolAddress((void**)&hA, g_hA);
    cudaGetSymbolAddress((void**)&hB, g_hB);

    const dim3 grid(H_ / BN, NSEQ / BM);      // (16, 32) = 512 blocks
    const float* hin = hA;                    // unused at t=0 (first flag)
    for (int t = 0; t < PT_; ++t) {
        float* hout = (t == PT_ - 1) ? out : ((t & 1) ? hB : hA);
        gru_step_kernel<<<grid, NTHREADS>>>(x, W, U, b, hin, hout, t, t == 0);
        hin = hout;
    }
    (void)in_sizes; (void)n_in; (void)out_size;
}

// round 4
// speedup vs baseline: 2.5805x; 2.5805x over previous
#include <cuda_runtime.h>
#include <cuda_fp16.h>
#include <cstdint>
#include <math.h>

// ---------------- problem constants ----------------
#define B_    128
#define T_    512
#define PT_   16
#define SKIP_ 32
#define NSEQ  4096

// ---------------- device-global scratch (no allocs allowed) ----------------
__device__ __half g_xp16[16u * 4096u * 1024u];   // x packed fp16 hi(0..511)|lo(512..1023), 134MB
__device__ __half g_wp16[1536u * 1024u];         // W packed (gate-interleaved cols)
__device__ __half g_up16[1536u * 1024u];         // U packed
__device__ float  g_xpf[65536u * 1536u];         // XP = x@W, packed col layout, 402MB
__device__ float  g_hf[2][NSEQ * 512u];          // hidden fp32 ping-pong
__device__ __half g_hp16[2][NSEQ * 1024u];       // hidden fp16 hi/lo ping-pong

// ---------------- smem layout (per stage, KC=32) ----------------
// A rows padded to 40 halves (80B): Ahi 128*80=10240, Alo 10240, Bhi 96*80=7680, Blo 7680
#define STAGE_BYTES 35840
#define SMEM_BYTES  (2 * STAGE_BYTES)     // 71680
#define OFF_ALO 10240
#define OFF_BHI 20480
#define OFF_BLO 28160

// ---------------- helpers ----------------
__device__ __forceinline__ uint32_t smem_u32(const void* p) {
    uint32_t a;
    asm("{ .reg .u64 t; cvta.to.shared.u64 t, %1; cvt.u32.u64 %0, t; }" : "=r"(a) : "l"(p));
    return a;
}
__device__ __forceinline__ void cp_async16(uint32_t s, const void* g) {
    asm volatile("cp.async.cg.shared.global [%0], [%1], 16;" :: "r"(s), "l"(g) : "memory");
}
__device__ __forceinline__ void cp_commit() { asm volatile("cp.async.commit_group;" ::: "memory"); }
template <int N> __device__ __forceinline__ void cp_wait() { asm volatile("cp.async.wait_group %0;" :: "n"(N) : "memory"); }

__device__ __forceinline__ void ldm4(uint32_t addr, uint32_t* r) {
    asm volatile("ldmatrix.sync.aligned.m8n8.x4.shared.b16 {%0,%1,%2,%3}, [%4];"
                 : "=r"(r[0]), "=r"(r[1]), "=r"(r[2]), "=r"(r[3]) : "r"(addr));
}
__device__ __forceinline__ void mma16816(float* d, const uint32_t* a, const uint32_t* b) {
    asm volatile("mma.sync.aligned.m16n8k16.row.col.f32.f16.f16.f32 "
                 "{%0,%1,%2,%3},{%4,%5,%6,%7},{%8,%9},{%0,%1,%2,%3};"
                 : "+f"(d[0]), "+f"(d[1]), "+f"(d[2]), "+f"(d[3])
                 : "r"(a[0]), "r"(a[1]), "r"(a[2]), "r"(a[3]), "r"(b[0]), "r"(b[1]));
}
__device__ __forceinline__ float sigmoidf_(float x) { return 1.f / (1.f + __expf(-x)); }

// ---------------- pack kernels ----------------
// packed B row pr = jt*96 + half*48 + g*16 + nn  ->  natural col g*512 + jt*32 + half*16 + nn
__global__ __launch_bounds__(256) void pack_wu16(const float* __restrict__ W, const float* __restrict__ U,
                                                 __half* __restrict__ Wp, __half* __restrict__ Up) {
    int idx = blockIdx.x * 256 + threadIdx.x;        // 0..98303
    const float* S = blockIdx.y ? U : W;
    __half* D = blockIdx.y ? Up : Wp;
    int pr = idx >> 6;
    int k0 = (idx & 63) * 8;
    int jt = pr / 96;
    int q  = pr - jt * 96;
    int half_ = q / 48;
    int q2 = q - half_ * 48;
    int g  = q2 >> 4;
    int nn = q2 & 15;
    int col = g * 512 + jt * 32 + half_ * 16 + nn;
    __align__(16) __half hi[8], lo[8];
#pragma unroll
    for (int i = 0; i < 8; ++i) {
        float v = S[(size_t)(k0 + i) * 1536 + col];
        __half h = __float2half_rn(v);
        hi[i] = h;
        lo[i] = __float2half_rn(v - __half2float(h));
    }
    *(uint4*)(D + (size_t)pr * 1024 + k0)       = *(const uint4*)hi;
    *(uint4*)(D + (size_t)pr * 1024 + 512 + k0) = *(const uint4*)lo;
}

__global__ __launch_bounds__(256) void pack_x16(const float* __restrict__ x, __half* __restrict__ Xp) {
    unsigned idx = blockIdx.x * 256 + threadIdx.x;   // 0..4194303
    unsigned t   = idx >> 18;
    unsigned rem = idx & 0x3FFFFu;
    unsigned m   = rem >> 6;
    unsigned k0  = (rem & 63) * 8;
    unsigned bb  = m >> 5, kk = m & 31;
    const float* src = x + ((size_t)bb * T_ + (size_t)(t * SKIP_ + kk)) * 512 + k0;
    float4 v0 = *(const float4*)(src);
    float4 v1 = *(const float4*)(src + 4);
    float f[8] = {v0.x, v0.y, v0.z, v0.w, v1.x, v1.y, v1.z, v1.w};
    __align__(16) __half hi[8], lo[8];
#pragma unroll
    for (int i = 0; i < 8; ++i) {
        __half h = __float2half_rn(f[i]);
        hi[i] = h;
        lo[i] = __float2half_rn(f[i] - __half2float(h));
    }
    __half* dst = Xp + ((size_t)t * 4096 + m) * 1024;
    *(uint4*)(dst + k0)       = *(const uint4*)hi;
    *(uint4*)(dst + 512 + k0) = *(const uint4*)lo;
}

// ---------------- loader ----------------
__device__ __forceinline__ void load_stage(uint32_t stg, const __half* __restrict__ Arow,
                                           const __half* __restrict__ Bm, int jt, int k0, int tid) {
    // A: 1024 16B chunks (hi 512 + lo 512)
#pragma unroll
    for (int i = 0; i < 4; ++i) {
        int a = tid + i * 256;
        int hilo = a >> 9;
        int idx  = a & 511;
        int row  = idx >> 2;
        int c    = idx & 3;
        const __half* g = Arow + (size_t)row * 1024 + hilo * 512 + k0 + c * 8;
        cp_async16(stg + hilo * OFF_ALO + row * 80 + c * 16, g);
    }
    // B: 768 chunks (hi 384 + lo 384)
#pragma unroll
    for (int i = 0; i < 3; ++i) {
        int b = tid + i * 256;
        int hilo = b / 384;
        int idx  = b - hilo * 384;
        int row  = idx >> 2;
        int c    = idx & 3;
        const __half* g = Bm + (size_t)(jt * 96 + row) * 1024 + hilo * 512 + k0 + c * 8;
        cp_async16(stg + OFF_BHI + hilo * 7680 + row * 80 + c * 16, g);
    }
}

// ---------------- fused GEMM (3-term fp16 split) ----------------
// mode 0: epilogue writes XP (packed cols).  mode 1: GRU gate epilogue.
__global__ __launch_bounds__(256) void gemm3(
    const __half* __restrict__ A, const __half* __restrict__ Bm,
    float* __restrict__ xpOut,
    const float* __restrict__ xpIn, const float* __restrict__ bias,
    const float* __restrict__ hprev, float* __restrict__ hout, __half* __restrict__ hpk,
    int mode, int first)
{
    extern __shared__ __align__(16) char smem[];
    uint32_t sb = smem_u32(smem);
    const int tid  = threadIdx.x;
    const int lane = tid & 31;
    const int wid  = tid >> 5;
    const int wm   = wid >> 1;       // 0..3
    const int wn   = wid & 1;        // 0..1
    const int jt   = blockIdx.x;     // 0..15
    const int mt   = blockIdx.y;

    float d[2][6][4];
#pragma unroll
    for (int a = 0; a < 2; ++a)
#pragma unroll
        for (int b = 0; b < 6; ++b)
#pragma unroll
            for (int c = 0; c < 4; ++c) d[a][b][c] = 0.f;

    if (!(mode == 1 && first)) {
        const __half* Arow = A + (size_t)mt * 128 * 1024;
        load_stage(sb, Arow, Bm, jt, 0, tid);
        cp_commit();

        const uint32_t aoff = (uint32_t)((wm * 32 + (lane & 15)) * 80 + (lane >> 4) * 16);
        const uint32_t boff = (uint32_t)((wn * 48 + (lane & 7) + ((lane >> 4) << 3)) * 80 + ((lane >> 3) & 1) * 16);

        for (int s = 0; s < 16; ++s) {
            if (s < 15) {
                load_stage(sb + ((s + 1) & 1) * STAGE_BYTES, Arow, Bm, jt, (s + 1) * 32, tid);
                cp_commit();
                cp_wait<1>();
            } else {
                cp_wait<0>();
            }
            __syncthreads();
            uint32_t stg = sb + (s & 1) * STAGE_BYTES;
#pragma unroll
            for (int k16 = 0; k16 < 2; ++k16) {
                uint32_t ah = stg + aoff + k16 * 32;
                uint32_t al = stg + OFF_ALO + aoff + k16 * 32;
                uint32_t bh = stg + OFF_BHI + boff + k16 * 32;
                uint32_t bl = stg + OFF_BLO + boff + k16 * 32;
                uint32_t ahi[2][4], alo[2][4], bhi[3][4], blo[3][4];
                ldm4(ah, ahi[0]);            ldm4(ah + 16 * 80, ahi[1]);
                ldm4(al, alo[0]);            ldm4(al + 16 * 80, alo[1]);
                ldm4(bh, bhi[0]);            ldm4(bh + 16 * 80, bhi[1]);  ldm4(bh + 32 * 80, bhi[2]);
                ldm4(bl, blo[0]);            ldm4(bl + 16 * 80, blo[1]);  ldm4(bl + 32 * 80, blo[2]);
#pragma unroll
                for (int mi = 0; mi < 2; ++mi)
#pragma unroll
                    for (int nj = 0; nj < 6; ++nj)
                        mma16816(d[mi][nj], ahi[mi], &bhi[nj >> 1][(nj & 1) * 2]);
#pragma unroll
                for (int mi = 0; mi < 2; ++mi)
#pragma unroll
                    for (int nj = 0; nj < 6; ++nj)
                        mma16816(d[mi][nj], ahi[mi], &blo[nj >> 1][(nj & 1) * 2]);
#pragma unroll
                for (int mi = 0; mi < 2; ++mi)
#pragma unroll
                    for (int nj = 0; nj < 6; ++nj)
                        mma16816(d[mi][nj], alo[mi], &bhi[nj >> 1][(nj & 1) * 2]);
            }
            __syncthreads();
        }
    }

    // ---------------- epilogue ----------------
    if (mode == 0) {
#pragma unroll
        for (int mi = 0; mi < 2; ++mi)
#pragma unroll
            for (int rh = 0; rh < 2; ++rh) {
                int mg = mt * 128 + wm * 32 + mi * 16 + (lane >> 2) + rh * 8;
#pragma unroll
                for (int nj = 0; nj < 6; ++nj) {
                    size_t pc = (size_t)mg * 1536 + jt * 96 + wn * 48 + nj * 8 + (lane & 3) * 2;
                    *(float2*)(xpOut + pc) = make_float2(d[mi][nj][rh * 2], d[mi][nj][rh * 2 + 1]);
                }
            }
    } else {
#pragma unroll
        for (int mi = 0; mi < 2; ++mi)
#pragma unroll
            for (int rh = 0; rh < 2; ++rh) {
                int mg = mt * 128 + wm * 32 + mi * 16 + (lane >> 2) + rh * 8;
#pragma unroll
                for (int nj = 0; nj < 2; ++nj) {
                    int cb   = nj * 8 + (lane & 3) * 2;
                    int colh = jt * 32 + wn * 16 + cb;               // h-column (0..511), even
                    size_t pcz = (size_t)mg * 1536 + jt * 96 + wn * 48 + cb;
                    float2 xz = *(const float2*)(xpIn + pcz);
                    float2 xr = *(const float2*)(xpIn + pcz + 16);
                    float2 xh = *(const float2*)(xpIn + pcz + 32);
                    float2 hp = make_float2(0.f, 0.f);
                    if (!first) hp = *(const float2*)(hprev + (size_t)mg * 512 + colh);
                    float2 b0z = *(const float2*)(bias + colh);
                    float2 b1z = *(const float2*)(bias + 1536 + colh);
                    float2 b0r = *(const float2*)(bias + 512 + colh);
                    float2 b1r = *(const float2*)(bias + 2048 + colh);
                    float2 b0h = *(const float2*)(bias + 1024 + colh);
                    float2 b1h = *(const float2*)(bias + 2560 + colh);
                    float xzv[2] = {xz.x, xz.y}, xrv[2] = {xr.x, xr.y}, xhv[2] = {xh.x, xh.y};
                    float hpv[2] = {hp.x, hp.y};
                    float b0zv[2] = {b0z.x, b0z.y}, b1zv[2] = {b1z.x, b1z.y};
                    float b0rv[2] = {b0r.x, b0r.y}, b1rv[2] = {b1r.x, b1r.y};
                    float b0hv[2] = {b0h.x, b0h.y}, b1hv[2] = {b1h.x, b1h.y};
                    float hn[2];
#pragma unroll
                    for (int cc = 0; cc < 2; ++cc) {
                        int r = rh * 2 + cc;
                        float zp  = d[mi][nj][r]     + xzv[cc] + b0zv[cc] + b1zv[cc];
                        float rp  = d[mi][nj + 2][r] + xrv[cc] + b0rv[cc] + b1rv[cc];
                        float xhp = xhv[cc] + b0hv[cc];
                        float rhp = d[mi][nj + 4][r] + b1hv[cc];
                        float z  = sigmoidf_(zp);
                        float rg = sigmoidf_(rp);
                        float hh = fmaxf(xhp + rg * rhp, 0.f);
                        hn[cc] = z * hpv[cc] + (1.f - z) * hh;
                    }
                    *(float2*)(hout + (size_t)mg * 512 + colh) = make_float2(hn[0], hn[1]);
                    __half h0 = __float2half_rn(hn[0]);
                    __half h1 = __float2half_rn(hn[1]);
                    __half l0 = __float2half_rn(hn[0] - __half2float(h0));
                    __half l1 = __float2half_rn(hn[1] - __half2float(h1));
                    *(__half2*)(hpk + (size_t)mg * 1024 + colh)       = __halves2half2(h0, h1);
                    *(__half2*)(hpk + (size_t)mg * 1024 + 512 + colh) = __halves2half2(l0, l1);
                }
            }
    }
}

// ---------------- host ----------------
extern "C" void kernel_launch(void* const* d_in, const int* in_sizes, int n_in,
                              void* d_out, int out_size) {
    const float* x = (const float*)d_in[0];
    const float* W = (const float*)d_in[1];
    const float* U = (const float*)d_in[2];
    const float* b = (const float*)d_in[3];
    float* out = (float*)d_out;

    __half *Xp, *Wp, *Up, *Hp0;
    float *XPf, *Hf0;
    cudaGetSymbolAddress((void**)&Xp, g_xp16);
    cudaGetSymbolAddress((void**)&Wp, g_wp16);
    cudaGetSymbolAddress((void**)&Up, g_up16);
    cudaGetSymbolAddress((void**)&XPf, g_xpf);
    cudaGetSymbolAddress((void**)&Hf0, g_hf);
    cudaGetSymbolAddress((void**)&Hp0, g_hp16);
    float*  Hf[2] = {Hf0, Hf0 + (size_t)NSEQ * 512};
    __half* Hp[2] = {Hp0, Hp0 + (size_t)NSEQ * 1024};

    static int smem_set = 0;
    if (!smem_set) {
        cudaFuncSetAttribute(gemm3, cudaFuncAttributeMaxDynamicSharedMemorySize, SMEM_BYTES);
        smem_set = 1;
    }

    pack_wu16<<<dim3(384, 2), 256>>>(W, U, Wp, Up);
    pack_x16<<<16384, 256>>>(x, Xp);

    // XP = x @ W for all 16 timesteps: M=65536
    gemm3<<<dim3(16, 512), 256, SMEM_BYTES>>>(Xp, Wp, XPf,
                                              nullptr, nullptr, nullptr, nullptr, nullptr, 0, 0);

    for (int t = 0; t < PT_; ++t) {
        const __half* Ahp = Hp[(t + 1) & 1];
        const float* hprev = Hf[(t + 1) & 1];
        float* ho = (t == PT_ - 1) ? out : Hf[t & 1];
        gemm3<<<dim3(16, 32), 256, SMEM_BYTES>>>(Ahp, Up, nullptr,
                                                 XPf + (size_t)t * 4096 * 1536, b,
                                                 hprev, ho, Hp[t & 1], 1, t == 0 ? 1 : 0);
    }
    (void)in_sizes; (void)n_in; (void)out_size;
}

// round 5
// speedup vs baseline: 2.6873x; 1.0414x over previous
#include <cuda_runtime.h>
#include <cuda_fp16.h>
#include <cstdint>
#include <math.h>

// ---------------- problem constants ----------------
#define B_    128
#define T_    512
#define PT_   16
#define SKIP_ 32
#define NSEQ  4096

// ---------------- device-global scratch (no allocs allowed) ----------------
__device__ __half g_xp16[16u * 4096u * 1024u];   // x packed fp16 hi(0..511)|lo(512..1023)
__device__ __half g_wp16[1536u * 1024u];         // W packed (gate-interleaved cols)
__device__ __half g_up16[1536u * 1024u];         // U packed
__device__ float  g_xpf[65536u * 1536u];         // XP = x@W, packed col layout
__device__ float  g_hf[2][NSEQ * 512u];          // hidden fp32 ping-pong
__device__ __half g_hp16[2][NSEQ * 1024u];       // hidden fp16 hi/lo ping-pong

// ---------------- smem layout (per stage, KC=32) ----------------
#define STAGE_BYTES 35840
#define SMEM_BYTES  (2 * STAGE_BYTES)
#define OFF_ALO 10240
#define OFF_BHI 20480
#define OFF_BLO 28160

// ---------------- helpers ----------------
__device__ __forceinline__ uint32_t smem_u32(const void* p) {
    uint32_t a;
    asm("{ .reg .u64 t; cvta.to.shared.u64 t, %1; cvt.u32.u64 %0, t; }" : "=r"(a) : "l"(p));
    return a;
}
__device__ __forceinline__ void cp_async16(uint32_t s, const void* g) {
    asm volatile("cp.async.cg.shared.global [%0], [%1], 16;" :: "r"(s), "l"(g) : "memory");
}
__device__ __forceinline__ void cp_commit() { asm volatile("cp.async.commit_group;" ::: "memory"); }
template <int N> __device__ __forceinline__ void cp_wait() { asm volatile("cp.async.wait_group %0;" :: "n"(N) : "memory"); }

__device__ __forceinline__ void ldm4(uint32_t addr, uint32_t* r) {
    asm volatile("ldmatrix.sync.aligned.m8n8.x4.shared.b16 {%0,%1,%2,%3}, [%4];"
                 : "=r"(r[0]), "=r"(r[1]), "=r"(r[2]), "=r"(r[3]) : "r"(addr));
}
__device__ __forceinline__ void mma16816(float* d, const uint32_t* a, const uint32_t* b) {
    asm volatile("mma.sync.aligned.m16n8k16.row.col.f32.f16.f16.f32 "
                 "{%0,%1,%2,%3},{%4,%5,%6,%7},{%8,%9},{%0,%1,%2,%3};"
                 : "+f"(d[0]), "+f"(d[1]), "+f"(d[2]), "+f"(d[3])
                 : "r"(a[0]), "r"(a[1]), "r"(a[2]), "r"(a[3]), "r"(b[0]), "r"(b[1]));
}
__device__ __forceinline__ float sigmoidf_(float x) { return 1.f / (1.f + __expf(-x)); }

// ---------------- pack kernels ----------------
__global__ __launch_bounds__(256) void pack_wu16(const float* __restrict__ W, const float* __restrict__ U,
                                                 __half* __restrict__ Wp, __half* __restrict__ Up) {
    int idx = blockIdx.x * 256 + threadIdx.x;
    const float* S = blockIdx.y ? U : W;
    __half* D = blockIdx.y ? Up : Wp;
    int pr = idx >> 6;
    int k0 = (idx & 63) * 8;
    int jt = pr / 96;
    int q  = pr - jt * 96;
    int half_ = q / 48;
    int q2 = q - half_ * 48;
    int g  = q2 >> 4;
    int nn = q2 & 15;
    int col = g * 512 + jt * 32 + half_ * 16 + nn;
    __align__(16) __half hi[8], lo[8];
#pragma unroll
    for (int i = 0; i < 8; ++i) {
        float v = S[(size_t)(k0 + i) * 1536 + col];
        __half h = __float2half_rn(v);
        hi[i] = h;
        lo[i] = __float2half_rn(v - __half2float(h));
    }
    *(uint4*)(D + (size_t)pr * 1024 + k0)       = *(const uint4*)hi;
    *(uint4*)(D + (size_t)pr * 1024 + 512 + k0) = *(const uint4*)lo;
}

__global__ __launch_bounds__(256) void pack_x16(const float* __restrict__ x, __half* __restrict__ Xp) {
    unsigned idx = blockIdx.x * 256 + threadIdx.x;
    unsigned t   = idx >> 18;
    unsigned rem = idx & 0x3FFFFu;
    unsigned m   = rem >> 6;
    unsigned k0  = (rem & 63) * 8;
    unsigned bb  = m >> 5, kk = m & 31;
    const float* src = x + ((size_t)bb * T_ + (size_t)(t * SKIP_ + kk)) * 512 + k0;
    float4 v0 = *(const float4*)(src);
    float4 v1 = *(const float4*)(src + 4);
    float f[8] = {v0.x, v0.y, v0.z, v0.w, v1.x, v1.y, v1.z, v1.w};
    __align__(16) __half hi[8], lo[8];
#pragma unroll
    for (int i = 0; i < 8; ++i) {
        __half h = __float2half_rn(f[i]);
        hi[i] = h;
        lo[i] = __float2half_rn(f[i] - __half2float(h));
    }
    __half* dst = Xp + ((size_t)t * 4096 + m) * 1024;
    *(uint4*)(dst + k0)       = *(const uint4*)hi;
    *(uint4*)(dst + 512 + k0) = *(const uint4*)lo;
}

// ---------------- loader ----------------
__device__ __forceinline__ void load_stage(uint32_t stg, const __half* __restrict__ Arow,
                                           const __half* __restrict__ Bm, int jt, int k0, int tid) {
#pragma unroll
    for (int i = 0; i < 4; ++i) {
        int a = tid + i * 256;
        int hilo = a >> 9;
        int idx  = a & 511;
        int row  = idx >> 2;
        int c    = idx & 3;
        const __half* g = Arow + (size_t)row * 1024 + hilo * 512 + k0 + c * 8;
        cp_async16(stg + hilo * OFF_ALO + row * 80 + c * 16, g);
    }
#pragma unroll
    for (int i = 0; i < 3; ++i) {
        int b = tid + i * 256;
        int hilo = b / 384;
        int idx  = b - hilo * 384;
        int row  = idx >> 2;
        int c    = idx & 3;
        const __half* g = Bm + (size_t)(jt * 96 + row) * 1024 + hilo * 512 + k0 + c * 8;
        cp_async16(stg + OFF_BHI + hilo * 7680 + row * 80 + c * 16, g);
    }
}

// ---------------- dual-role fused GEMM ----------------
// role 0 (blockIdx.z==0): GRU step t  — GEMM h@U (skipped when first) + gate epilogue.
// role 1 (blockIdx.z==1, or xp_only): XP[xp_slot] = x_t@W — GEMM + XP-write epilogue.
__global__ __launch_bounds__(256) void gemm3(
    const __half* __restrict__ Xp,      // packed x, all t
    const __half* __restrict__ Wp,
    const __half* __restrict__ Up,
    float* __restrict__ XPf,            // 16-slot XP buffer
    const float* __restrict__ bias,
    const __half* __restrict__ hpack_in,
    const float* __restrict__ hprev,
    float* __restrict__ hout,
    __half* __restrict__ hpk,
    int t, int xp_slot, int xp_only, int first)
{
    extern __shared__ __align__(16) char smem[];
    uint32_t sb = smem_u32(smem);
    const int tid  = threadIdx.x;
    const int lane = tid & 31;
    const int wid  = tid >> 5;
    const int wm   = wid >> 1;
    const int wn   = wid & 1;
    const int jt   = blockIdx.x;
    const int mt   = blockIdx.y;
    const int role = xp_only ? 1 : (int)blockIdx.z;

    float d[2][6][4];
#pragma unroll
    for (int a = 0; a < 2; ++a)
#pragma unroll
        for (int b = 0; b < 6; ++b)
#pragma unroll
            for (int c = 0; c < 4; ++c) d[a][b][c] = 0.f;

    const int do_gemm = (role == 1) || !first;
    if (do_gemm) {
        const __half* A  = (role == 1) ? (Xp + (size_t)xp_slot * 4096u * 1024u) : hpack_in;
        const __half* Bm = (role == 1) ? Wp : Up;
        const __half* Arow = A + (size_t)mt * 128 * 1024;
        load_stage(sb, Arow, Bm, jt, 0, tid);
        cp_commit();

        const uint32_t aoff = (uint32_t)((wm * 32 + (lane & 15)) * 80 + (lane >> 4) * 16);
        const uint32_t boff = (uint32_t)((wn * 48 + (lane & 7) + ((lane >> 4) << 3)) * 80 + ((lane >> 3) & 1) * 16);

        for (int s = 0; s < 16; ++s) {
            if (s < 15) {
                load_stage(sb + ((s + 1) & 1) * STAGE_BYTES, Arow, Bm, jt, (s + 1) * 32, tid);
                cp_commit();
                cp_wait<1>();
            } else {
                cp_wait<0>();
            }
            __syncthreads();
            uint32_t stg = sb + (s & 1) * STAGE_BYTES;
#pragma unroll
            for (int k16 = 0; k16 < 2; ++k16) {
                uint32_t ah = stg + aoff + k16 * 32;
                uint32_t al = stg + OFF_ALO + aoff + k16 * 32;
                uint32_t bh = stg + OFF_BHI + boff + k16 * 32;
                uint32_t bl = stg + OFF_BLO + boff + k16 * 32;
                uint32_t ahi[2][4], alo[2][4], bhi[3][4], blo[3][4];
                ldm4(ah, ahi[0]);  ldm4(ah + 16 * 80, ahi[1]);
                ldm4(al, alo[0]);  ldm4(al + 16 * 80, alo[1]);
                ldm4(bh, bhi[0]);  ldm4(bh + 16 * 80, bhi[1]);  ldm4(bh + 32 * 80, bhi[2]);
                ldm4(bl, blo[0]);  ldm4(bl + 16 * 80, blo[1]);  ldm4(bl + 32 * 80, blo[2]);
#pragma unroll
                for (int mi = 0; mi < 2; ++mi)
#pragma unroll
                    for (int nj = 0; nj < 6; ++nj)
                        mma16816(d[mi][nj], ahi[mi], &bhi[nj >> 1][(nj & 1) * 2]);
#pragma unroll
                for (int mi = 0; mi < 2; ++mi)
#pragma unroll
                    for (int nj = 0; nj < 6; ++nj)
                        mma16816(d[mi][nj], ahi[mi], &blo[nj >> 1][(nj & 1) * 2]);
#pragma unroll
                for (int mi = 0; mi < 2; ++mi)
#pragma unroll
                    for (int nj = 0; nj < 6; ++nj)
                        mma16816(d[mi][nj], alo[mi], &bhi[nj >> 1][(nj & 1) * 2]);
            }
            __syncthreads();
        }
    }

    // ---------------- epilogues ----------------
    if (role == 1) {
        float* xpOut = XPf + (size_t)xp_slot * 4096u * 1536u;
#pragma unroll
        for (int mi = 0; mi < 2; ++mi)
#pragma unroll
            for (int rh = 0; rh < 2; ++rh) {
                int mg = mt * 128 + wm * 32 + mi * 16 + (lane >> 2) + rh * 8;
#pragma unroll
                for (int nj = 0; nj < 6; ++nj) {
                    size_t pc = (size_t)mg * 1536 + jt * 96 + wn * 48 + nj * 8 + (lane & 3) * 2;
                    *(float2*)(xpOut + pc) = make_float2(d[mi][nj][rh * 2], d[mi][nj][rh * 2 + 1]);
                }
            }
    } else {
        const float* xpIn = XPf + (size_t)t * 4096u * 1536u;
#pragma unroll
        for (int mi = 0; mi < 2; ++mi)
#pragma unroll
            for (int rh = 0; rh < 2; ++rh) {
                int mg = mt * 128 + wm * 32 + mi * 16 + (lane >> 2) + rh * 8;
#pragma unroll
                for (int nj = 0; nj < 2; ++nj) {
                    int cb   = nj * 8 + (lane & 3) * 2;
                    int colh = jt * 32 + wn * 16 + cb;
                    size_t pcz = (size_t)mg * 1536 + jt * 96 + wn * 48 + cb;
                    float2 xz = *(const float2*)(xpIn + pcz);
                    float2 xr = *(const float2*)(xpIn + pcz + 16);
                    float2 xh = *(const float2*)(xpIn + pcz + 32);
                    float2 hp = make_float2(0.f, 0.f);
                    if (!first) hp = *(const float2*)(hprev + (size_t)mg * 512 + colh);
                    float2 b0z = *(const float2*)(bias + colh);
                    float2 b1z = *(const float2*)(bias + 1536 + colh);
                    float2 b0r = *(const float2*)(bias + 512 + colh);
                    float2 b1r = *(const float2*)(bias + 2048 + colh);
                    float2 b0h = *(const float2*)(bias + 1024 + colh);
                    float2 b1h = *(const float2*)(bias + 2560 + colh);
                    float xzv[2] = {xz.x, xz.y}, xrv[2] = {xr.x, xr.y}, xhv[2] = {xh.x, xh.y};
                    float hpv[2] = {hp.x, hp.y};
                    float b0zv[2] = {b0z.x, b0z.y}, b1zv[2] = {b1z.x, b1z.y};
                    float b0rv[2] = {b0r.x, b0r.y}, b1rv[2] = {b1r.x, b1r.y};
                    float b0hv[2] = {b0h.x, b0h.y}, b1hv[2] = {b1h.x, b1h.y};
                    float hn[2];
#pragma unroll
                    for (int cc = 0; cc < 2; ++cc) {
                        int r = rh * 2 + cc;
                        float zp  = d[mi][nj][r]     + xzv[cc] + b0zv[cc] + b1zv[cc];
                        float rp  = d[mi][nj + 2][r] + xrv[cc] + b0rv[cc] + b1rv[cc];
                        float xhp = xhv[cc] + b0hv[cc];
                        float rhp = d[mi][nj + 4][r] + b1hv[cc];
                        float z  = sigmoidf_(zp);
                        float rg = sigmoidf_(rp);
                        float hh = fmaxf(xhp + rg * rhp, 0.f);
                        hn[cc] = z * hpv[cc] + (1.f - z) * hh;
                    }
                    *(float2*)(hout + (size_t)mg * 512 + colh) = make_float2(hn[0], hn[1]);
                    __half h0 = __float2half_rn(hn[0]);
                    __half h1 = __float2half_rn(hn[1]);
                    __half l0 = __float2half_rn(hn[0] - __half2float(h0));
                    __half l1 = __float2half_rn(hn[1] - __half2float(h1));
                    *(__half2*)(hpk + (size_t)mg * 1024 + colh)       = __halves2half2(h0, h1);
                    *(__half2*)(hpk + (size_t)mg * 1024 + 512 + colh) = __halves2half2(l0, l1);
                }
            }
    }
}

// ---------------- host ----------------
extern "C" void kernel_launch(void* const* d_in, const int* in_sizes, int n_in,
                              void* d_out, int out_size) {
    const float* x = (const float*)d_in[0];
    const float* W = (const float*)d_in[1];
    const float* U = (const float*)d_in[2];
    const float* b = (const float*)d_in[3];
    float* out = (float*)d_out;

    __half *Xp, *Wp, *Up, *Hp0;
    float *XPf, *Hf0;
    cudaGetSymbolAddress((void**)&Xp, g_xp16);
    cudaGetSymbolAddress((void**)&Wp, g_wp16);
    cudaGetSymbolAddress((void**)&Up, g_up16);
    cudaGetSymbolAddress((void**)&XPf, g_xpf);
    cudaGetSymbolAddress((void**)&Hf0, g_hf);
    cudaGetSymbolAddress((void**)&Hp0, g_hp16);
    float*  Hf[2] = {Hf0, Hf0 + (size_t)NSEQ * 512};
    __half* Hp[2] = {Hp0, Hp0 + (size_t)NSEQ * 1024};

    static int smem_set = 0;
    if (!smem_set) {
        cudaFuncSetAttribute(gemm3, cudaFuncAttributeMaxDynamicSharedMemorySize, SMEM_BYTES);
        smem_set = 1;
    }

    pack_wu16<<<dim3(384, 2), 256>>>(W, U, Wp, Up);
    pack_x16<<<16384, 256>>>(x, Xp);

    // Prelaunch: XP[0] only
    gemm3<<<dim3(16, 32, 1), 256, SMEM_BYTES>>>(Xp, Wp, Up, XPf, b,
                                                nullptr, nullptr, nullptr, nullptr,
                                                /*t=*/0, /*xp_slot=*/0, /*xp_only=*/1, /*first=*/0);

    for (int t = 0; t < PT_; ++t) {
        const __half* Ahp  = Hp[(t + 1) & 1];
        const float* hprev = Hf[(t + 1) & 1];
        float* ho = (t == PT_ - 1) ? out : Hf[t & 1];
        const int has_xp = (t < PT_ - 1);
        gemm3<<<dim3(16, 32, has_xp ? 2 : 1), 256, SMEM_BYTES>>>(
            Xp, Wp, Up, XPf, b, Ahp, hprev, ho, Hp[t & 1],
            /*t=*/t, /*xp_slot=*/t + 1, /*xp_only=*/0, /*first=*/t == 0 ? 1 : 0);
    }
    (void)in_sizes; (void)n_in; (void)out_size;
}

// round 6
// speedup vs baseline: 4.2446x; 1.5795x over previous
#include <cuda_runtime.h>
#include <cuda_fp16.h>
#include <cstdint>
#include <math.h>

// ---------------- problem constants ----------------
#define B_    128
#define T_    512
#define PT_   16
#define SKIP_ 32
#define NSEQ  4096

// ---------------- device-global scratch (no allocs allowed) ----------------
__device__ __half g_xp16[16u * 4096u * 512u];    // x packed fp16 (hi only), 67MB
__device__ __half g_wp16[1536u * 1024u];         // W packed hi|lo (gate-interleaved cols)
__device__ __half g_up16[1536u * 1024u];         // U packed hi|lo
__device__ float  g_xpf[65536u * 1536u];         // XP = x@W, packed col layout
__device__ float  g_hf[2][NSEQ * 512u];          // hidden fp32 ping-pong
__device__ __half g_hp16[2][NSEQ * 512u];        // hidden fp16 (hi only) ping-pong

// ---------------- smem layout (per stage, KC=64) ----------------
// rows padded to 144B (128B data + 16B): A 128*144=18432, Bhi 96*144=13824, Blo 13824
#define ROWB        144
#define STAGE_BYTES 46080
#define SMEM_BYTES  (2 * STAGE_BYTES)    // 92160
#define OFF_BHI     18432
#define OFF_BLO     32256

// ---------------- helpers ----------------
__device__ __forceinline__ uint32_t smem_u32(const void* p) {
    uint32_t a;
    asm("{ .reg .u64 t; cvta.to.shared.u64 t, %1; cvt.u32.u64 %0, t; }" : "=r"(a) : "l"(p));
    return a;
}
__device__ __forceinline__ void cp_async16(uint32_t s, const void* g) {
    asm volatile("cp.async.cg.shared.global [%0], [%1], 16;" :: "r"(s), "l"(g) : "memory");
}
__device__ __forceinline__ void cp_commit() { asm volatile("cp.async.commit_group;" ::: "memory"); }
template <int N> __device__ __forceinline__ void cp_wait() { asm volatile("cp.async.wait_group %0;" :: "n"(N) : "memory"); }

__device__ __forceinline__ void ldm4(uint32_t addr, uint32_t* r) {
    asm volatile("ldmatrix.sync.aligned.m8n8.x4.shared.b16 {%0,%1,%2,%3}, [%4];"
                 : "=r"(r[0]), "=r"(r[1]), "=r"(r[2]), "=r"(r[3]) : "r"(addr));
}
__device__ __forceinline__ void mma16816(float* d, const uint32_t* a, const uint32_t* b) {
    asm volatile("mma.sync.aligned.m16n8k16.row.col.f32.f16.f16.f32 "
                 "{%0,%1,%2,%3},{%4,%5,%6,%7},{%8,%9},{%0,%1,%2,%3};"
                 : "+f"(d[0]), "+f"(d[1]), "+f"(d[2]), "+f"(d[3])
                 : "r"(a[0]), "r"(a[1]), "r"(a[2]), "r"(a[3]), "r"(b[0]), "r"(b[1]));
}
__device__ __forceinline__ float sigmoidf_(float x) { return 1.f / (1.f + __expf(-x)); }

// ---------------- pack kernels ----------------
// packed B row pr = jt*96 + half*48 + g*16 + nn  ->  natural col g*512 + jt*32 + half*16 + nn
__global__ __launch_bounds__(256) void pack_wu16(const float* __restrict__ W, const float* __restrict__ U,
                                                 __half* __restrict__ Wp, __half* __restrict__ Up) {
    int idx = blockIdx.x * 256 + threadIdx.x;
    const float* S = blockIdx.y ? U : W;
    __half* D = blockIdx.y ? Up : Wp;
    int pr = idx >> 6;
    int k0 = (idx & 63) * 8;
    int jt = pr / 96;
    int q  = pr - jt * 96;
    int half_ = q / 48;
    int q2 = q - half_ * 48;
    int g  = q2 >> 4;
    int nn = q2 & 15;
    int col = g * 512 + jt * 32 + half_ * 16 + nn;
    __align__(16) __half hi[8], lo[8];
#pragma unroll
    for (int i = 0; i < 8; ++i) {
        float v = S[(size_t)(k0 + i) * 1536 + col];
        __half h = __float2half_rn(v);
        hi[i] = h;
        lo[i] = __float2half_rn(v - __half2float(h));
    }
    *(uint4*)(D + (size_t)pr * 1024 + k0)       = *(const uint4*)hi;
    *(uint4*)(D + (size_t)pr * 1024 + 512 + k0) = *(const uint4*)lo;
}

__global__ __launch_bounds__(256) void pack_x16(const float* __restrict__ x, __half* __restrict__ Xp) {
    unsigned idx = blockIdx.x * 256 + threadIdx.x;   // 0..4194303 chunks of 8
    unsigned t   = idx >> 18;
    unsigned rem = idx & 0x3FFFFu;
    unsigned m   = rem >> 6;
    unsigned k0  = (rem & 63) * 8;
    unsigned bb  = m >> 5, kk = m & 31;
    const float* src = x + ((size_t)bb * T_ + (size_t)(t * SKIP_ + kk)) * 512 + k0;
    float4 v0 = *(const float4*)(src);
    float4 v1 = *(const float4*)(src + 4);
    float f[8] = {v0.x, v0.y, v0.z, v0.w, v1.x, v1.y, v1.z, v1.w};
    __align__(16) __half hi[8];
#pragma unroll
    for (int i = 0; i < 8; ++i) hi[i] = __float2half_rn(f[i]);
    __half* dst = Xp + ((size_t)t * 4096 + m) * 512;
    *(uint4*)(dst + k0) = *(const uint4*)hi;
}

// ---------------- loader (KC=64 stage) ----------------
__device__ __forceinline__ void load_stage(uint32_t stg, const __half* __restrict__ Arow,
                                           const __half* __restrict__ Bm, int jt, int k0, int tid) {
    // A (hi only): 128 rows x 8 chunks = 1024
#pragma unroll
    for (int i = 0; i < 4; ++i) {
        int a = tid + i * 256;
        int row = a >> 3;
        int c   = a & 7;
        cp_async16(stg + row * ROWB + c * 16, Arow + (size_t)row * 512 + k0 + c * 8);
    }
    // B hi+lo: 2 x 96 rows x 8 chunks = 1536
#pragma unroll
    for (int i = 0; i < 6; ++i) {
        int b = tid + i * 256;
        int hilo = (b >= 768) ? 1 : 0;
        int idx  = b - hilo * 768;
        int row  = idx >> 3;
        int c    = idx & 7;
        cp_async16(stg + OFF_BHI + hilo * (OFF_BLO - OFF_BHI) + row * ROWB + c * 16,
                   Bm + (size_t)(jt * 96 + row) * 1024 + hilo * 512 + k0 + c * 8);
    }
}

// ---------------- dual-role fused GEMM (2-term fp16: Ahi*(Bhi+Blo)) ----------------
__global__ __launch_bounds__(256) void gemm3(
    const __half* __restrict__ Xp,
    const __half* __restrict__ Wp,
    const __half* __restrict__ Up,
    float* __restrict__ XPf,
    const float* __restrict__ bias,
    const __half* __restrict__ hpack_in,
    const float* __restrict__ hprev,
    float* __restrict__ hout,
    __half* __restrict__ hpk,
    int t, int xp_slot, int xp_only, int first)
{
    extern __shared__ __align__(16) char smem[];
    uint32_t sb = smem_u32(smem);
    const int tid  = threadIdx.x;
    const int lane = tid & 31;
    const int wid  = tid >> 5;
    const int wm   = wid >> 1;
    const int wn   = wid & 1;
    const int jt   = blockIdx.x;
    const int mt   = blockIdx.y;
    const int role = xp_only ? 1 : (int)blockIdx.z;

    float d[2][6][4];
#pragma unroll
    for (int a = 0; a < 2; ++a)
#pragma unroll
        for (int b = 0; b < 6; ++b)
#pragma unroll
            for (int c = 0; c < 4; ++c) d[a][b][c] = 0.f;

    const int do_gemm = (role == 1) || !first;
    if (do_gemm) {
        const __half* A  = (role == 1) ? (Xp + (size_t)xp_slot * 4096u * 512u) : hpack_in;
        const __half* Bm = (role == 1) ? Wp : Up;
        const __half* Arow = A + (size_t)mt * 128 * 512;
        load_stage(sb, Arow, Bm, jt, 0, tid);
        cp_commit();

        const uint32_t aoff = (uint32_t)((wm * 32 + (lane & 15)) * ROWB + (lane >> 4) * 16);
        const uint32_t boff = (uint32_t)((wn * 48 + (lane & 7) + ((lane >> 4) << 3)) * ROWB + ((lane >> 3) & 1) * 16);

        for (int s = 0; s < 8; ++s) {
            if (s < 7) {
                load_stage(sb + ((s + 1) & 1) * STAGE_BYTES, Arow, Bm, jt, (s + 1) * 64, tid);
                cp_commit();
                cp_wait<1>();
            } else {
                cp_wait<0>();
            }
            __syncthreads();
            uint32_t stg = sb + (s & 1) * STAGE_BYTES;
#pragma unroll
            for (int k16 = 0; k16 < 4; ++k16) {
                uint32_t ah = stg + aoff + k16 * 32;
                uint32_t bh = stg + OFF_BHI + boff + k16 * 32;
                uint32_t bl = stg + OFF_BLO + boff + k16 * 32;
                uint32_t ahi[2][4], bhi[3][4], blo[3][4];
                ldm4(ah, ahi[0]);  ldm4(ah + 16 * ROWB, ahi[1]);
                ldm4(bh, bhi[0]);  ldm4(bh + 16 * ROWB, bhi[1]);  ldm4(bh + 32 * ROWB, bhi[2]);
                ldm4(bl, blo[0]);  ldm4(bl + 16 * ROWB, blo[1]);  ldm4(bl + 32 * ROWB, blo[2]);
#pragma unroll
                for (int mi = 0; mi < 2; ++mi)
#pragma unroll
                    for (int nj = 0; nj < 6; ++nj)
                        mma16816(d[mi][nj], ahi[mi], &bhi[nj >> 1][(nj & 1) * 2]);
#pragma unroll
                for (int mi = 0; mi < 2; ++mi)
#pragma unroll
                    for (int nj = 0; nj < 6; ++nj)
                        mma16816(d[mi][nj], ahi[mi], &blo[nj >> 1][(nj & 1) * 2]);
            }
            __syncthreads();
        }
    }

    // ---------------- epilogues ----------------
    if (role == 1) {
        float* xpOut = XPf + (size_t)xp_slot * 4096u * 1536u;
#pragma unroll
        for (int mi = 0; mi < 2; ++mi)
#pragma unroll
            for (int rh = 0; rh < 2; ++rh) {
                int mg = mt * 128 + wm * 32 + mi * 16 + (lane >> 2) + rh * 8;
#pragma unroll
                for (int nj = 0; nj < 6; ++nj) {
                    size_t pc = (size_t)mg * 1536 + jt * 96 + wn * 48 + nj * 8 + (lane & 3) * 2;
                    *(float2*)(xpOut + pc) = make_float2(d[mi][nj][rh * 2], d[mi][nj][rh * 2 + 1]);
                }
            }
    } else {
        const float* xpIn = XPf + (size_t)t * 4096u * 1536u;
#pragma unroll
        for (int mi = 0; mi < 2; ++mi)
#pragma unroll
            for (int rh = 0; rh < 2; ++rh) {
                int mg = mt * 128 + wm * 32 + mi * 16 + (lane >> 2) + rh * 8;
#pragma unroll
                for (int nj = 0; nj < 2; ++nj) {
                    int cb   = nj * 8 + (lane & 3) * 2;
                    int colh = jt * 32 + wn * 16 + cb;
                    size_t pcz = (size_t)mg * 1536 + jt * 96 + wn * 48 + cb;
                    float2 xz = *(const float2*)(xpIn + pcz);
                    float2 xr = *(const float2*)(xpIn + pcz + 16);
                    float2 xh = *(const float2*)(xpIn + pcz + 32);
                    float2 hp = make_float2(0.f, 0.f);
                    if (!first) hp = *(const float2*)(hprev + (size_t)mg * 512 + colh);
                    float2 b0z = *(const float2*)(bias + colh);
                    float2 b1z = *(const float2*)(bias + 1536 + colh);
                    float2 b0r = *(const float2*)(bias + 512 + colh);
                    float2 b1r = *(const float2*)(bias + 2048 + colh);
                    float2 b0h = *(const float2*)(bias + 1024 + colh);
                    float2 b1h = *(const float2*)(bias + 2560 + colh);
                    float xzv[2] = {xz.x, xz.y}, xrv[2] = {xr.x, xr.y}, xhv[2] = {xh.x, xh.y};
                    float hpv[2] = {hp.x, hp.y};
                    float b0zv[2] = {b0z.x, b0z.y}, b1zv[2] = {b1z.x, b1z.y};
                    float b0rv[2] = {b0r.x, b0r.y}, b1rv[2] = {b1r.x, b1r.y};
                    float b0hv[2] = {b0h.x, b0h.y}, b1hv[2] = {b1h.x, b1h.y};
                    float hn[2];
#pragma unroll
                    for (int cc = 0; cc < 2; ++cc) {
                        int r = rh * 2 + cc;
                        float zp  = d[mi][nj][r]     + xzv[cc] + b0zv[cc] + b1zv[cc];
                        float rp  = d[mi][nj + 2][r] + xrv[cc] + b0rv[cc] + b1rv[cc];
                        float xhp = xhv[cc] + b0hv[cc];
                        float rhp = d[mi][nj + 4][r] + b1hv[cc];
                        float z  = sigmoidf_(zp);
                        float rg = sigmoidf_(rp);
                        float hh = fmaxf(xhp + rg * rhp, 0.f);
                        hn[cc] = z * hpv[cc] + (1.f - z) * hh;
                    }
                    *(float2*)(hout + (size_t)mg * 512 + colh) = make_float2(hn[0], hn[1]);
                    *(__half2*)(hpk + (size_t)mg * 512 + colh) =
                        __halves2half2(__float2half_rn(hn[0]), __float2half_rn(hn[1]));
                }
            }
    }
}

// ---------------- host ----------------
extern "C" void kernel_launch(void* const* d_in, const int* in_sizes, int n_in,
                              void* d_out, int out_size) {
    const float* x = (const float*)d_in[0];
    const float* W = (const float*)d_in[1];
    const float* U = (const float*)d_in[2];
    const float* b = (const float*)d_in[3];
    float* out = (float*)d_out;

    __half *Xp, *Wp, *Up, *Hp0;
    float *XPf, *Hf0;
    cudaGetSymbolAddress((void**)&Xp, g_xp16);
    cudaGetSymbolAddress((void**)&Wp, g_wp16);
    cudaGetSymbolAddress((void**)&Up, g_up16);
    cudaGetSymbolAddress((void**)&XPf, g_xpf);
    cudaGetSymbolAddress((void**)&Hf0, g_hf);
    cudaGetSymbolAddress((void**)&Hp0, g_hp16);
    float*  Hf[2] = {Hf0, Hf0 + (size_t)NSEQ * 512};
    __half* Hp[2] = {Hp0, Hp0 + (size_t)NSEQ * 512};

    static int smem_set = 0;
    if (!smem_set) {
        cudaFuncSetAttribute(gemm3, cudaFuncAttributeMaxDynamicSharedMemorySize, SMEM_BYTES);
        smem_set = 1;
    }

    pack_wu16<<<dim3(384, 2), 256>>>(W, U, Wp, Up);
    pack_x16<<<16384, 256>>>(x, Xp);

    // Prelaunch: XP[0] only
    gemm3<<<dim3(16, 32, 1), 256, SMEM_BYTES>>>(Xp, Wp, Up, XPf, b,
                                                nullptr, nullptr, nullptr, nullptr,
                                                0, 0, 1, 0);

    for (int t = 0; t < PT_; ++t) {
        const __half* Ahp  = Hp[(t + 1) & 1];
        const float* hprev = Hf[(t + 1) & 1];
        float* ho = (t == PT_ - 1) ? out : Hf[t & 1];
        const int has_xp = (t < PT_ - 1);
        gemm3<<<dim3(16, 32, has_xp ? 2 : 1), 256, SMEM_BYTES>>>(
            Xp, Wp, Up, XPf, b, Ahp, hprev, ho, Hp[t & 1],
            t, t + 1, 0, t == 0 ? 1 : 0);
    }
    (void)in_sizes; (void)n_in; (void)out_size;
}